// round 6
// baseline (speedup 1.0000x reference)
#include <cuda_runtime.h>

#define N_NODES 10000
#define N_EDGES 320000
#define F 128
#define F4 32     // F/4
#define CLS 64
#define CLS4 16

#define MT 626            // ceil(10000/16) m-tiles of 16 rows
#define KS 16             // K/8 k-steps
#define AFRAG_N (MT * KS * 32)     // uint4 entries per operand
#define WFRAG_PER_LAYER (16 * KS * 32 * 2)   // floats (max 16 ntiles)

// ---------------- device scratch (no allocations allowed) ----------------
__device__ int   g_rowptr[N_NODES + 1];
__device__ int   g_cnt[N_NODES];
__device__ int   g_cur[N_NODES];
__device__ int   g_eids[N_EDGES];
__device__ int   g_srcs[N_EDGES];
__device__ float g_A[N_NODES * F];
__device__ float g_B[N_NODES * F];
__device__ float g_C[N_NODES * F];
__device__ float g_Bhi[AFRAG_N * 4];
__device__ float g_Blo[AFRAG_N * 4];
__device__ float g_Whi[5 * WFRAG_PER_LAYER];
__device__ float g_Wlo[5 * WFRAG_PER_LAYER];

// ---------------- CSR build ----------------
__global__ void k_zero_cnt() {
    int i = blockIdx.x * blockDim.x + threadIdx.x;
    if (i < N_NODES) g_cnt[i] = 0;
}

__global__ void k_hist(const int* __restrict__ dst) {
    int e = blockIdx.x * blockDim.x + threadIdx.x;
    if (e < N_EDGES) atomicAdd(&g_cnt[dst[e]], 1);
}

__global__ void k_scan() {
    __shared__ int sh[1024];
    const int t = threadIdx.x;
    const int ITEMS = 10;
    int base = t * ITEMS;
    int loc[ITEMS];
    int run = 0;
    #pragma unroll
    for (int j = 0; j < ITEMS; j++) {
        int i = base + j;
        int c = (i < N_NODES) ? g_cnt[i] : 0;
        loc[j] = run;
        run += c;
    }
    sh[t] = run;
    __syncthreads();
    for (int off = 1; off < 1024; off <<= 1) {
        int v = (t >= off) ? sh[t - off] : 0;
        __syncthreads();
        sh[t] += v;
        __syncthreads();
    }
    int excl = sh[t] - run;
    #pragma unroll
    for (int j = 0; j < ITEMS; j++) {
        int i = base + j;
        if (i < N_NODES) {
            int rp = excl + loc[j];
            g_rowptr[i] = rp;
            g_cur[i]    = rp;
        }
    }
    if (t == 1023) g_rowptr[N_NODES] = sh[1023];
}

__global__ void k_scatter(const int* __restrict__ src, const int* __restrict__ dst) {
    int e = blockIdx.x * blockDim.x + threadIdx.x;
    if (e < N_EDGES) {
        int p = atomicAdd(&g_cur[dst[e]], 1);
        g_eids[p] = e;
        g_srcs[p] = src[e];
    }
}

// ---------------- gather kernels ----------------
#define ADD4(dstv, srcv) { (dstv).x += (srcv).x; (dstv).y += (srcv).y; \
                           (dstv).z += (srcv).z; (dstv).w += (srcv).w; }

__global__ void k_A1(const float* __restrict__ ef) {
    int w    = (blockIdx.x * blockDim.x + threadIdx.x) >> 5;
    int lane = threadIdx.x & 31;
    if (w >= N_NODES) return;
    int r0 = g_rowptr[w], r1 = g_rowptr[w + 1];
    const float4* E4 = (const float4*)ef;
    float4 a0 = make_float4(0.f,0.f,0.f,0.f), a1 = a0, a2 = a0, a3 = a0;
    for (int base = r0; base < r1; base += 32) {
        int rem = r1 - base;
        int n = rem < 32 ? rem : 32;
        int idx = (lane < n) ? g_eids[base + lane] : 0;
        int j = 0;
        for (; j + 4 <= n; j += 4) {
            int s0 = __shfl_sync(0xffffffffu, idx, j);
            int s1 = __shfl_sync(0xffffffffu, idx, j + 1);
            int s2 = __shfl_sync(0xffffffffu, idx, j + 2);
            int s3 = __shfl_sync(0xffffffffu, idx, j + 3);
            float4 x0 = E4[s0 * F4 + lane];
            float4 x1 = E4[s1 * F4 + lane];
            float4 x2 = E4[s2 * F4 + lane];
            float4 x3 = E4[s3 * F4 + lane];
            ADD4(a0, x0); ADD4(a1, x1); ADD4(a2, x2); ADD4(a3, x3);
        }
        for (; j < n; j++) {
            int s = __shfl_sync(0xffffffffu, idx, j);
            float4 xv = E4[s * F4 + lane];
            ADD4(a0, xv);
        }
    }
    a0.x += a1.x + a2.x + a3.x; a0.y += a1.y + a2.y + a3.y;
    a0.z += a1.z + a2.z + a3.z; a0.w += a1.w + a2.w + a3.w;
    float inv = 1.f / (float)(r1 - r0);
    a0.x *= inv; a0.y *= inv; a0.z *= inv; a0.w *= inv;
    ((float4*)g_A)[w * F4 + lane] = a0;
}

__global__ void k_Af(const float* __restrict__ bias) {
    int w    = (blockIdx.x * blockDim.x + threadIdx.x) >> 5;
    int lane = threadIdx.x & 31;
    if (w >= N_NODES) return;
    int r0 = g_rowptr[w], r1 = g_rowptr[w + 1];
    const float4* C4 = (const float4*)g_C;
    float4 cd = C4[w * F4 + lane];
    float4 bb = ((const float4*)bias)[lane];
    float4 cb;
    cb.x = cd.x * 0.5f + bb.x; cb.y = cd.y * 0.5f + bb.y;
    cb.z = cd.z * 0.5f + bb.z; cb.w = cd.w * 0.5f + bb.w;
    float4 a0 = make_float4(0.f,0.f,0.f,0.f), a1 = a0, a2 = a0, a3 = a0;
    for (int base = r0; base < r1; base += 32) {
        int rem = r1 - base;
        int n = rem < 32 ? rem : 32;
        int idx = (lane < n) ? g_srcs[base + lane] : 0;
        int j = 0;
        for (; j + 4 <= n; j += 4) {
            int s0 = __shfl_sync(0xffffffffu, idx, j);
            int s1 = __shfl_sync(0xffffffffu, idx, j + 1);
            int s2 = __shfl_sync(0xffffffffu, idx, j + 2);
            int s3 = __shfl_sync(0xffffffffu, idx, j + 3);
            float4 x0 = C4[s0 * F4 + lane];
            float4 x1 = C4[s1 * F4 + lane];
            float4 x2 = C4[s2 * F4 + lane];
            float4 x3 = C4[s3 * F4 + lane];
            a0.x += fmaxf(fmaf(x0.x, 0.5f, cb.x), 0.f);
            a0.y += fmaxf(fmaf(x0.y, 0.5f, cb.y), 0.f);
            a0.z += fmaxf(fmaf(x0.z, 0.5f, cb.z), 0.f);
            a0.w += fmaxf(fmaf(x0.w, 0.5f, cb.w), 0.f);
            a1.x += fmaxf(fmaf(x1.x, 0.5f, cb.x), 0.f);
            a1.y += fmaxf(fmaf(x1.y, 0.5f, cb.y), 0.f);
            a1.z += fmaxf(fmaf(x1.z, 0.5f, cb.z), 0.f);
            a1.w += fmaxf(fmaf(x1.w, 0.5f, cb.w), 0.f);
            a2.x += fmaxf(fmaf(x2.x, 0.5f, cb.x), 0.f);
            a2.y += fmaxf(fmaf(x2.y, 0.5f, cb.y), 0.f);
            a2.z += fmaxf(fmaf(x2.z, 0.5f, cb.z), 0.f);
            a2.w += fmaxf(fmaf(x2.w, 0.5f, cb.w), 0.f);
            a3.x += fmaxf(fmaf(x3.x, 0.5f, cb.x), 0.f);
            a3.y += fmaxf(fmaf(x3.y, 0.5f, cb.y), 0.f);
            a3.z += fmaxf(fmaf(x3.z, 0.5f, cb.z), 0.f);
            a3.w += fmaxf(fmaf(x3.w, 0.5f, cb.w), 0.f);
        }
        for (; j < n; j++) {
            int s = __shfl_sync(0xffffffffu, idx, j);
            float4 xv = C4[s * F4 + lane];
            a0.x += fmaxf(fmaf(xv.x, 0.5f, cb.x), 0.f);
            a0.y += fmaxf(fmaf(xv.y, 0.5f, cb.y), 0.f);
            a0.z += fmaxf(fmaf(xv.z, 0.5f, cb.z), 0.f);
            a0.w += fmaxf(fmaf(xv.w, 0.5f, cb.w), 0.f);
        }
    }
    a0.x += a1.x + a2.x + a3.x; a0.y += a1.y + a2.y + a3.y;
    a0.z += a1.z + a2.z + a3.z; a0.w += a1.w + a2.w + a3.w;
    float inv = 1.f / (float)(r1 - r0);
    a0.x *= inv; a0.y *= inv; a0.z *= inv; a0.w *= inv;
    ((float4*)g_A)[w * F4 + lane] = a0;
}

__global__ void k_B() {
    int w    = (blockIdx.x * blockDim.x + threadIdx.x) >> 5;
    int lane = threadIdx.x & 31;
    if (w >= N_NODES) return;
    int r0 = g_rowptr[w], r1 = g_rowptr[w + 1];
    const float4* A4 = (const float4*)g_A;
    float4 a0 = make_float4(0.f,0.f,0.f,0.f), a1 = a0, a2 = a0, a3 = a0;
    for (int base = r0; base < r1; base += 32) {
        int rem = r1 - base;
        int n = rem < 32 ? rem : 32;
        int idx = (lane < n) ? g_srcs[base + lane] : 0;
        int j = 0;
        for (; j + 4 <= n; j += 4) {
            int s0 = __shfl_sync(0xffffffffu, idx, j);
            int s1 = __shfl_sync(0xffffffffu, idx, j + 1);
            int s2 = __shfl_sync(0xffffffffu, idx, j + 2);
            int s3 = __shfl_sync(0xffffffffu, idx, j + 3);
            float4 x0 = A4[s0 * F4 + lane];
            float4 x1 = A4[s1 * F4 + lane];
            float4 x2 = A4[s2 * F4 + lane];
            float4 x3 = A4[s3 * F4 + lane];
            ADD4(a0, x0); ADD4(a1, x1); ADD4(a2, x2); ADD4(a3, x3);
        }
        for (; j < n; j++) {
            int s = __shfl_sync(0xffffffffu, idx, j);
            float4 xv = A4[s * F4 + lane];
            ADD4(a0, xv);
        }
    }
    a0.x += a1.x + a2.x + a3.x; a0.y += a1.y + a2.y + a3.y;
    a0.z += a1.z + a2.z + a3.z; a0.w += a1.w + a2.w + a3.w;
    ((float4*)g_B)[w * F4 + lane] = a0;
}

// ---------------- tf32 split helpers ----------------
__device__ __forceinline__ float tf32_hi(float x) {
    return __uint_as_float(__float_as_uint(x) & 0xFFFFE000u);
}
__device__ __forceinline__ void tf32_split(float x, float& h, float& l) {
    h = tf32_hi(x);
    l = tf32_hi(x - h);
}

// Split W[layer] into tf32 hi/lo in B-operand fragment order.
// frag b0 = Bmat[k=t][n=g] = W[nt*8+g][ks*8+t], b1 at k=t+4.
__global__ void k_splitW(const float* __restrict__ W0, const float* __restrict__ W1,
                         const float* __restrict__ W2, const float* __restrict__ W3,
                         const float* __restrict__ W4) {
    int layer = blockIdx.y;
    int idx = blockIdx.x * 256 + threadIdx.x;   // nt*512 + ks*32 + lane
    int ntCount = (layer == 4) ? 8 : 16;
    if (idx >= ntCount * 512) return;
    int nt = idx >> 9;
    int ks = (idx >> 5) & 15;
    int lane = idx & 31;
    int g = lane >> 2, t = lane & 3;
    const float* W = (layer == 0) ? W0 : (layer == 1) ? W1 : (layer == 2) ? W2
                   : (layer == 3) ? W3 : W4;
    float w0 = W[(nt * 8 + g) * F + ks * 8 + t];
    float w1 = W[(nt * 8 + g) * F + ks * 8 + t + 4];
    float h0, l0, h1, l1;
    tf32_split(w0, h0, l0);
    tf32_split(w1, h1, l1);
    int base = layer * WFRAG_PER_LAYER + idx * 2;
    g_Whi[base] = h0; g_Whi[base + 1] = h1;
    g_Wlo[base] = l0; g_Wlo[base + 1] = l1;
}

// Split g_B into tf32 hi/lo in A-operand fragment order.
// a0=(g,t) a1=(g+8,t) a2=(g,t+4) a3=(g+8,t+4); rows zero-padded past N_NODES.
__global__ void k_splitB() {
    int idx = blockIdx.x * 256 + threadIdx.x;   // (mt*16+ks)*32 + lane
    if (idx >= MT * KS * 32) return;
    int lane = idx & 31;
    int ks = (idx >> 5) & 15;
    int mt = idx >> 9;
    int g = lane >> 2, t = lane & 3;
    int r0 = mt * 16 + g, r1 = r0 + 8;
    int c0 = ks * 8 + t, c1 = c0 + 4;
    float v0 = (r0 < N_NODES) ? g_B[r0 * F + c0] : 0.f;
    float v1 = (r1 < N_NODES) ? g_B[r1 * F + c0] : 0.f;
    float v2 = (r0 < N_NODES) ? g_B[r0 * F + c1] : 0.f;
    float v3 = (r1 < N_NODES) ? g_B[r1 * F + c1] : 0.f;
    float h0,l0,h1,l1,h2,l2,h3,l3;
    tf32_split(v0, h0, l0); tf32_split(v1, h1, l1);
    tf32_split(v2, h2, l2); tf32_split(v3, h3, l3);
    ((float4*)g_Bhi)[idx] = make_float4(h0, h1, h2, h3);
    ((float4*)g_Blo)[idx] = make_float4(l0, l1, l2, l3);
}

// ---------------- tensor-core GEMM: C = B @ W^T via 3xTF32 -----------------
#define MMA_TF32(c, a, b) \
    asm volatile("mma.sync.aligned.m16n8k8.row.col.f32.tf32.tf32.f32 " \
        "{%0,%1,%2,%3}, {%4,%5,%6,%7}, {%8,%9}, {%0,%1,%2,%3};" \
        : "+f"((c)[0]), "+f"((c)[1]), "+f"((c)[2]), "+f"((c)[3]) \
        : "r"((a).x), "r"((a).y), "r"((a).z), "r"((a).w), \
          "r"((b).x), "r"((b).y))

// 8 warps: warp w -> mtile bx*4+(w&3), ntiles [(w>>2)*NTPW, +NTPW).
// Output N = NTPW*16 (8 -> 128, 4 -> 64).
template <int NTPW>
__global__ __launch_bounds__(256) void k_gemm_mma(int layer) {
    const int w = threadIdx.x >> 5, lane = threadIdx.x & 31;
    const int mt = blockIdx.x * 4 + (w & 3);
    if (mt >= MT) return;
    const int ntbase = (w >> 2) * NTPW;
    const float* __restrict__ Whi = g_Whi + layer * WFRAG_PER_LAYER;
    const float* __restrict__ Wlo = g_Wlo + layer * WFRAG_PER_LAYER;
    const uint4* __restrict__ AH = (const uint4*)g_Bhi;
    const uint4* __restrict__ AL = (const uint4*)g_Blo;

    float acc[NTPW][4];
    #pragma unroll
    for (int j = 0; j < NTPW; j++) {
        acc[j][0] = 0.f; acc[j][1] = 0.f; acc[j][2] = 0.f; acc[j][3] = 0.f;
    }

    #pragma unroll 4
    for (int ks = 0; ks < KS; ks++) {
        uint4 ah = AH[(mt * 16 + ks) * 32 + lane];
        uint4 al = AL[(mt * 16 + ks) * 32 + lane];
        #pragma unroll
        for (int j = 0; j < NTPW; j++) {
            int nt = ntbase + j;
            int wb = ((nt * 16 + ks) * 32 + lane) * 2;
            uint2 bh = *(const uint2*)(Whi + wb);
            uint2 bl = *(const uint2*)(Wlo + wb);
            MMA_TF32(acc[j], ah, bh);
            MMA_TF32(acc[j], al, bh);
            MMA_TF32(acc[j], ah, bl);
        }
    }

    const int NS = NTPW * 16;
    const int g = lane >> 2, t = lane & 3;
    const int r0 = mt * 16 + g, r1 = r0 + 8;
    #pragma unroll
    for (int j = 0; j < NTPW; j++) {
        int col = (ntbase + j) * 8 + 2 * t;
        if (r0 < N_NODES)
            *(float2*)(g_C + r0 * NS + col) = make_float2(acc[j][0], acc[j][1]);
        if (r1 < N_NODES)
            *(float2*)(g_C + r1 * NS + col) = make_float2(acc[j][2], acc[j][3]);
    }
}

// out[e] = 0.5*(C5[src]+C5[dst]) + b5   (C5 stride = 64)
__global__ void k_out(const int* __restrict__ src, const int* __restrict__ dst,
                      const float* __restrict__ b5, float* __restrict__ out) {
    int i = blockIdx.x * blockDim.x + threadIdx.x;
    if (i >= N_EDGES * CLS4) return;
    int e = i >> 4;
    int c = i & 15;
    int s = src[e], d = dst[e];
    const float4* C4 = (const float4*)g_C;
    float4 xs = C4[s * CLS4 + c];
    float4 xd = C4[d * CLS4 + c];
    float4 bb = ((const float4*)b5)[c];
    float4 o;
    o.x = (xs.x + xd.x) * 0.5f + bb.x;
    o.y = (xs.y + xd.y) * 0.5f + bb.y;
    o.z = (xs.z + xd.z) * 0.5f + bb.z;
    o.w = (xs.w + xd.w) * 0.5f + bb.w;
    ((float4*)out)[i] = o;
}

// ---------------- launch ----------------
extern "C" void kernel_launch(void* const* d_in, const int* in_sizes, int n_in,
                              void* d_out, int out_size) {
    const float* ef  = (const float*)d_in[0];
    const int*   src = (const int*)d_in[1];
    const int*   dst = (const int*)d_in[2];
    const float* W[5] = {(const float*)d_in[3], (const float*)d_in[5],
                         (const float*)d_in[7], (const float*)d_in[9],
                         (const float*)d_in[11]};
    const float* b[5] = {(const float*)d_in[4], (const float*)d_in[6],
                         (const float*)d_in[8], (const float*)d_in[10],
                         (const float*)d_in[12]};
    float* out = (float*)d_out;

    k_zero_cnt<<<(N_NODES + 255) / 256, 256>>>();
    k_hist<<<(N_EDGES + 255) / 256, 256>>>(dst);
    k_scan<<<1, 1024>>>();
    k_scatter<<<(N_EDGES + 255) / 256, 256>>>(src, dst);
    k_splitW<<<dim3(32, 5), 256>>>(W[0], W[1], W[2], W[3], W[4]);

    const int NODE_GRID = (N_NODES + 7) / 8;        // warp per node, 8/block
    const int SPLITB_GRID = (MT * KS * 32) / 256;   // 1252
    const int GEMM_GRID = (MT + 3) / 4;             // 157

    // layer 1
    k_A1<<<NODE_GRID, 256>>>(ef);
    k_B<<<NODE_GRID, 256>>>();
    k_splitB<<<SPLITB_GRID, 256>>>();
    k_gemm_mma<8><<<GEMM_GRID, 256>>>(0);
    // layers 2..4
    for (int l = 1; l < 4; l++) {
        k_Af<<<NODE_GRID, 256>>>(b[l - 1]);
        k_B<<<NODE_GRID, 256>>>();
        k_splitB<<<SPLITB_GRID, 256>>>();
        k_gemm_mma<8><<<GEMM_GRID, 256>>>(l);
    }
    // layer 5 (N = 64)
    k_Af<<<NODE_GRID, 256>>>(b[3]);
    k_B<<<NODE_GRID, 256>>>();
    k_splitB<<<SPLITB_GRID, 256>>>();
    k_gemm_mma<4><<<GEMM_GRID, 256>>>(4);

    k_out<<<(N_EDGES * CLS4 + 255) / 256, 256>>>(src, dst, b[4], out);
}